// round 13
// baseline (speedup 1.0000x reference)
#include <cuda_runtime.h>
#include <cstdint>

#define NBLK 296            // 148 SMs x 2 CTAs: exactly one wave
#define NTHR 256
#define NWARP (NTHR / 32)
#define STRIDE (NBLK * NTHR)
#define NSTAGE 4
#define SARRS 6             // m0,m1,m2,s0,s1,s2 staged in smem
#define STAGE_F4 (SARRS * NTHR)
#define STAGE_BYTES (STAGE_F4 * 16)            // 24576
#define SMEM_BYTES (NSTAGE * STAGE_BYTES)      // 98304 per CTA

// Per-block partial sums (deterministic reduction, no data atomics).
__device__ float g_part_p[NBLK];
__device__ float g_part_ll[NBLK];
__device__ float g_part_np[NBLK];
__device__ unsigned g_ticket = 0;   // self-resetting last-block-done counter

__device__ __forceinline__ float frcp(float x) {
    float y;
    asm("rcp.approx.f32 %0, %1;" : "=f"(y) : "f"(x));
    return y;
}
__device__ __forceinline__ float fex2(float x) {
    float y;
    asm("ex2.approx.f32 %0, %1;" : "=f"(y) : "f"(x));
    return y;
}

struct Acc { float p, ll, np; };

// Binned mixture probability, log2-domain (saturation matches reference clamp).
__device__ __forceinline__ float comp_prob(float m, float t, float s) {
    const float EPS = 1e-8f;
    const float HB  = 0.05f;
    const float L2E = 1.4426950408889634f;
    float il = frcp(s + EPS) * L2E;
    float a  = (m - t) * il;
    float b  = HB * il;
    float eu = fex2(a - b);
    float el = fex2(a + b);
    float den = frcp((1.f + eu) * (1.f + el));
    return fmaxf((el - eu) * den, EPS);
}

__device__ __forceinline__ void process_elem(
    float p, float t,
    float m0, float s0, float w0,
    float m1, float s1, float w1,
    float m2, float s2, float w2,
    Acc& a)
{
    const float EPS = 1e-8f;

    float lik = w0 * comp_prob(m0, t, s0);
    lik = fmaf(w1, comp_prob(m1, t, s1), lik);
    lik = fmaf(w2, comp_prob(m2, t, s2), lik);

    bool paid = (t > 0.f);
    float ll = __logf(lik + EPS);
    if (paid) { a.ll += ll; a.np += 1.f; }

    float q = paid ? p : (1.f - p);
    a.p -= fmaxf(__logf(q), -100.f);
}

// 16-byte cp.async (.cg: L2-only fill, no RF transit).
__device__ __forceinline__ void cpa16(uint32_t dst, const float4* src) {
    asm volatile("cp.async.cg.shared.global [%0], [%1], 16;"
                 :: "r"(dst), "l"(src) : "memory");
}

// Register-resident arrays: p, t, w0, w1, w2 (5 x float4 = 20 regs/buffer).
struct V5 { float4 p, t, w0, w1, w2; };

__global__ void __launch_bounds__(NTHR, 2) zimol_fused(
    const float* __restrict__ pp, const float* __restrict__ mu,
    const float* __restrict__ sg, const float* __restrict__ wt,
    const float* __restrict__ tv, float* __restrict__ out, int B)
{
    extern __shared__ float4 sbuf[];   // [NSTAGE][SARRS][NTHR]

    const int nvec4 = B >> 2;
    const int tid = threadIdx.x;
    const int bid = blockIdx.x;
    const int idx = bid * NTHR + tid;
    const int n = (idx < nvec4) ? (nvec4 - idx + STRIDE - 1) / STRIDE : 0;

    const float4* pp4 = reinterpret_cast<const float4*>(pp);
    const float4* tv4 = reinterpret_cast<const float4*>(tv);
    const float4* mu4 = reinterpret_cast<const float4*>(mu);
    const float4* sg4 = reinterpret_cast<const float4*>(sg);
    const float4* wt4 = reinterpret_cast<const float4*>(wt);

    const uint32_t sbase =
        (uint32_t)__cvta_generic_to_shared(sbuf) + (uint32_t)tid * 16u;

    Acc a = {0.f, 0.f, 0.f};

    // Issue stage k's 6 x 16B cp.async into this thread's private slots.
    auto issue_ms = [&](int k) {
        int v = idx + k * STRIDE;
        if (v < nvec4) {
            uint32_t d = sbase + (uint32_t)(k & (NSTAGE - 1)) * (uint32_t)STAGE_BYTES;
            cpa16(d + 0u * (NTHR * 16u), mu4 + v);
            cpa16(d + 1u * (NTHR * 16u), mu4 + nvec4 + v);
            cpa16(d + 2u * (NTHR * 16u), mu4 + 2 * nvec4 + v);
            cpa16(d + 3u * (NTHR * 16u), sg4 + v);
            cpa16(d + 4u * (NTHR * 16u), sg4 + nvec4 + v);
            cpa16(d + 5u * (NTHR * 16u), sg4 + 2 * nvec4 + v);
        }
    };

    auto load_v5 = [&](V5& b, int k) {
        int v = idx + k * STRIDE;
        if (v < nvec4) {
            b.p  = __ldg(pp4 + v);
            b.t  = __ldg(tv4 + v);
            b.w0 = __ldg(wt4 + v);
            b.w1 = __ldg(wt4 + nvec4 + v);
            b.w2 = __ldg(wt4 + 2 * nvec4 + v);
        }
    };

    auto compute = [&](const V5& b, int k) {
        int v = idx + k * STRIDE;
        if (v >= nvec4) return;
        const float4* sb = sbuf + (k & (NSTAGE - 1)) * STAGE_F4 + tid;
        float4 M0 = sb[0 * NTHR], M1 = sb[1 * NTHR], M2 = sb[2 * NTHR];
        float4 S0 = sb[3 * NTHR], S1 = sb[4 * NTHR], S2 = sb[5 * NTHR];
        process_elem(b.p.x, b.t.x, M0.x, S0.x, b.w0.x,
                     M1.x, S1.x, b.w1.x, M2.x, S2.x, b.w2.x, a);
        process_elem(b.p.y, b.t.y, M0.y, S0.y, b.w0.y,
                     M1.y, S1.y, b.w1.y, M2.y, S2.y, b.w2.y, a);
        process_elem(b.p.z, b.t.z, M0.z, S0.z, b.w0.z,
                     M1.z, S1.z, b.w1.z, M2.z, S2.z, b.w2.z, a);
        process_elem(b.p.w, b.t.w, M0.w, S0.w, b.w0.w,
                     M1.w, S1.w, b.w1.w, M2.w, S2.w, b.w2.w, a);
    };

    // ---- Prologue: 3 cp.async stages ahead + reg buffer for iter 0 ----
    V5 rA, rB;
    #pragma unroll
    for (int s = 0; s < NSTAGE - 1; s++) {
        issue_ms(s);
        asm volatile("cp.async.commit_group;" ::: "memory");
    }
    load_v5(rA, 0);

    // ---- Main loop: barrier-free, per-thread private slots ----
    for (int k = 0; k < n; k++) {
        // Wait until stage k's cp.async group has landed (keep 2 newer in flight).
        asm volatile("cp.async.wait_group 2;" ::: "memory");
        // Prefetch registers for k+1 while computing k.
        if (k & 1) { load_v5(rA, k + 1); compute(rB, k); }
        else       { load_v5(rB, k + 1); compute(rA, k); }
        // Refill the slot just freed (stage k+3); reads of slot (k-1) finished
        // during compute(k-1) in program order, so reuse is safe.
        issue_ms(k + NSTAGE - 1);
        asm volatile("cp.async.commit_group;" ::: "memory");
    }

    // Scalar tail (B not divisible by 4) — robustness; no-op for B = 4M.
    int tail = B & 3;
    if (tail) {
        int base = nvec4 << 2;
        if (idx < tail) {
            int j = base + idx;
            process_elem(pp[j], tv[j],
                         mu[0 * B + j], sg[0 * B + j], wt[0 * B + j],
                         mu[1 * B + j], sg[1 * B + j], wt[1 * B + j],
                         mu[2 * B + j], sg[2 * B + j], wt[2 * B + j], a);
        }
    }

    // ---- Block reduction (all float, shuffle + tiny smem) ----
    #pragma unroll
    for (int o = 16; o > 0; o >>= 1) {
        a.p  += __shfl_down_sync(0xffffffffu, a.p,  o);
        a.ll += __shfl_down_sync(0xffffffffu, a.ll, o);
        a.np += __shfl_down_sync(0xffffffffu, a.np, o);
    }

    __shared__ float shp[NWARP], shl[NWARP], shn[NWARP];
    __shared__ bool s_last;
    int wid  = tid >> 5;
    int lane = tid & 31;
    if (lane == 0) { shp[wid] = a.p; shl[wid] = a.ll; shn[wid] = a.np; }
    __syncthreads();

    if (tid == 0) {
        float vp = 0.f, vl = 0.f, vn = 0.f;
        #pragma unroll
        for (int k = 0; k < NWARP; k++) { vp += shp[k]; vl += shl[k]; vn += shn[k]; }
        g_part_p[bid]  = vp;
        g_part_ll[bid] = vl;
        g_part_np[bid] = vn;
        __threadfence();
        unsigned t = atomicAdd(&g_ticket, 1u);
        s_last = (t == (unsigned)(NBLK - 1));
        if (s_last) g_ticket = 0u;   // self-reset: deterministic across replays
    }
    __syncthreads();

    // ---- Last block finalizes (float, 296 partials) ----
    if (s_last) {
        float sp = 0.f, sl = 0.f, sn = 0.f;
        for (int k = tid; k < NBLK; k += NTHR) {
            sp += g_part_p[k];
            sl += g_part_ll[k];
            sn += g_part_np[k];
        }
        #pragma unroll
        for (int o = 16; o > 0; o >>= 1) {
            sp += __shfl_down_sync(0xffffffffu, sp, o);
            sl += __shfl_down_sync(0xffffffffu, sl, o);
            sn += __shfl_down_sync(0xffffffffu, sn, o);
        }
        if (lane == 0) { shp[wid] = sp; shl[wid] = sl; shn[wid] = sn; }
        __syncthreads();
        if (tid == 0) {
            float vp = 0.f, vl = 0.f, vn = 0.f;
            #pragma unroll
            for (int k = 0; k < NWARP; k++) { vp += shp[k]; vl += shl[k]; vn += shn[k]; }
            float purchase = vp / (float)B;
            float ltv = (vn > 0.f) ? -(vl / fmaxf(vn, 1.f)) : 0.f;
            out[0] = purchase + ltv;
        }
    }
}

extern "C" void kernel_launch(void* const* d_in, const int* in_sizes, int n_in,
                              void* d_out, int out_size)
{
    const float* pp = (const float*)d_in[0];  // predicted_purchase_prob (B,)
    const float* mu = (const float*)d_in[1];  // mu     (K,B)
    const float* sg = (const float*)d_in[2];  // sigma  (K,B)
    const float* wt = (const float*)d_in[3];  // weight (K,B)
    const float* tv = (const float*)d_in[4];  // true_values (B,)
    int B = in_sizes[0];

    // Opt-in to 96 KB dynamic smem per CTA (idempotent; not a stream op).
    cudaFuncSetAttribute(zimol_fused,
                         cudaFuncAttributeMaxDynamicSharedMemorySize, SMEM_BYTES);
    zimol_fused<<<NBLK, NTHR, SMEM_BYTES>>>(pp, mu, sg, wt, tv, (float*)d_out, B);
}

// round 14
// speedup vs baseline: 1.0504x; 1.0504x over previous
#include <cuda_runtime.h>

#define NBLK 296            // 148 SMs x 2 resident CTAs: exactly one wave
#define NTHR 256
#define NWARP (NTHR / 32)
#define STRIDE (NBLK * NTHR)

// Per-block partial sums (deterministic reduction, no data atomics).
__device__ float g_part_p[NBLK];
__device__ float g_part_ll[NBLK];
__device__ float g_part_np[NBLK];
__device__ unsigned g_ticket = 0;   // self-resetting last-block-done counter

__device__ __forceinline__ float frcp(float x) {
    float y;
    asm("rcp.approx.f32 %0, %1;" : "=f"(y) : "f"(x));
    return y;
}
__device__ __forceinline__ float fex2(float x) {
    float y;
    asm("ex2.approx.f32 %0, %1;" : "=f"(y) : "f"(x));
    return y;
}

struct Acc { float p, ll, np; };

// Full iteration payload: 11 float4s.
struct V11 {
    float4 p, t;
    float4 m0, m1, m2;
    float4 s0, s1, s2;
    float4 w0, w1, w2;
};

// Binned mixture probability, log2-domain (saturation matches reference clamp:
// overflow -> den inf -> rcp 0 -> 0/NaN; fmax(.,EPS)=EPS).
__device__ __forceinline__ float comp_prob(float m, float t, float s) {
    const float EPS = 1e-8f;
    const float HB  = 0.05f;
    const float L2E = 1.4426950408889634f;
    float il = frcp(s + EPS) * L2E;
    float a  = (m - t) * il;
    float b  = HB * il;
    float eu = fex2(a - b);
    float el = fex2(a + b);
    float den = frcp((1.f + eu) * (1.f + el));
    return fmaxf((el - eu) * den, EPS);
}

// ---- split loads: 3 sub-batches so ptxas can use separate scoreboards ----
__device__ __forceinline__ void load_g0(V11& b, int v, int nvec,
    const float4* __restrict__ tv4, const float4* __restrict__ mu4,
    const float4* __restrict__ sg4, const float4* __restrict__ wt4)
{
    b.t  = __ldg(tv4 + v);
    b.m0 = __ldg(mu4 + v);
    b.s0 = __ldg(sg4 + v);
    b.w0 = __ldg(wt4 + v);
}
__device__ __forceinline__ void load_g1(V11& b, int v, int nvec,
    const float4* __restrict__ mu4, const float4* __restrict__ sg4,
    const float4* __restrict__ wt4)
{
    b.m1 = __ldg(mu4 + nvec + v);
    b.s1 = __ldg(sg4 + nvec + v);
    b.w1 = __ldg(wt4 + nvec + v);
}
__device__ __forceinline__ void load_g2(V11& b, int v, int nvec,
    const float4* __restrict__ pp4, const float4* __restrict__ mu4,
    const float4* __restrict__ sg4, const float4* __restrict__ wt4)
{
    b.m2 = __ldg(mu4 + 2 * nvec + v);
    b.s2 = __ldg(sg4 + 2 * nvec + v);
    b.w2 = __ldg(wt4 + 2 * nvec + v);
    b.p  = __ldg(pp4 + v);
}

// ---- component-major compute phases ----
__device__ __forceinline__ void phase0(const V11& b, float* lik) {
    lik[0] = b.w0.x * comp_prob(b.m0.x, b.t.x, b.s0.x);
    lik[1] = b.w0.y * comp_prob(b.m0.y, b.t.y, b.s0.y);
    lik[2] = b.w0.z * comp_prob(b.m0.z, b.t.z, b.s0.z);
    lik[3] = b.w0.w * comp_prob(b.m0.w, b.t.w, b.s0.w);
}
__device__ __forceinline__ void phase1(const V11& b, float* lik) {
    lik[0] = fmaf(b.w1.x, comp_prob(b.m1.x, b.t.x, b.s1.x), lik[0]);
    lik[1] = fmaf(b.w1.y, comp_prob(b.m1.y, b.t.y, b.s1.y), lik[1]);
    lik[2] = fmaf(b.w1.z, comp_prob(b.m1.z, b.t.z, b.s1.z), lik[2]);
    lik[3] = fmaf(b.w1.w, comp_prob(b.m1.w, b.t.w, b.s1.w), lik[3]);
}
__device__ __forceinline__ void phase2(const V11& b, float* lik, Acc& a) {
    const float EPS = 1e-8f;
    lik[0] = fmaf(b.w2.x, comp_prob(b.m2.x, b.t.x, b.s2.x), lik[0]);
    lik[1] = fmaf(b.w2.y, comp_prob(b.m2.y, b.t.y, b.s2.y), lik[1]);
    lik[2] = fmaf(b.w2.z, comp_prob(b.m2.z, b.t.z, b.s2.z), lik[2]);
    lik[3] = fmaf(b.w2.w, comp_prob(b.m2.w, b.t.w, b.s2.w), lik[3]);

    const float t4[4] = {b.t.x, b.t.y, b.t.z, b.t.w};
    const float p4[4] = {b.p.x, b.p.y, b.p.z, b.p.w};
    #pragma unroll
    for (int e = 0; e < 4; e++) {
        bool paid = (t4[e] > 0.f);
        float ll = __logf(lik[e] + EPS);
        if (paid) { a.ll += ll; a.np += 1.f; }
        float q = paid ? p4[e] : (1.f - p4[e]);
        a.p -= fmaxf(__logf(q), -100.f);
    }
}

__device__ __forceinline__ void process_scalar(
    float p, float t,
    float m0, float s0, float w0,
    float m1, float s1, float w1,
    float m2, float s2, float w2,
    Acc& a)
{
    const float EPS = 1e-8f;
    float lik = w0 * comp_prob(m0, t, s0);
    lik = fmaf(w1, comp_prob(m1, t, s1), lik);
    lik = fmaf(w2, comp_prob(m2, t, s2), lik);
    bool paid = (t > 0.f);
    float ll = __logf(lik + EPS);
    if (paid) { a.ll += ll; a.np += 1.f; }
    float q = paid ? p : (1.f - p);
    a.p -= fmaxf(__logf(q), -100.f);
}

__global__ void __launch_bounds__(NTHR, 2) zimol_fused(
    const float* __restrict__ pp, const float* __restrict__ mu,
    const float* __restrict__ sg, const float* __restrict__ wt,
    const float* __restrict__ tv, float* __restrict__ out, int B)
{
    const int nvec = B >> 2;
    Acc a = {0.f, 0.f, 0.f};

    const float4* pp4 = reinterpret_cast<const float4*>(pp);
    const float4* tv4 = reinterpret_cast<const float4*>(tv);
    const float4* mu4 = reinterpret_cast<const float4*>(mu);
    const float4* sg4 = reinterpret_cast<const float4*>(sg);
    const float4* wt4 = reinterpret_cast<const float4*>(wt);

    const int idx = blockIdx.x * NTHR + threadIdx.x;
    int n = (idx < nvec) ? (nvec - idx + STRIDE - 1) / STRIDE : 0;

    V11 bufA, bufB;
    if (n > 0) {
        load_g0(bufA, idx, nvec, tv4, mu4, sg4, wt4);
        load_g1(bufA, idx, nvec, mu4, sg4, wt4);
        load_g2(bufA, idx, nvec, pp4, mu4, sg4, wt4);
    }

    // Software pipeline: loads for k+1 interleaved between compute phases of k,
    // in the order each sub-batch is consumed (t/m0/s0/w0 first, p last).
    float lik[4];
    int i = 0;
    #pragma unroll 2
    for (; i + 1 < n; i++) {
        int vn = idx + (i + 1) * STRIDE;
        if (i & 1) {
            load_g0(bufA, vn, nvec, tv4, mu4, sg4, wt4);
            phase0(bufB, lik);
            load_g1(bufA, vn, nvec, mu4, sg4, wt4);
            phase1(bufB, lik);
            load_g2(bufA, vn, nvec, pp4, mu4, sg4, wt4);
            phase2(bufB, lik, a);
        } else {
            load_g0(bufB, vn, nvec, tv4, mu4, sg4, wt4);
            phase0(bufA, lik);
            load_g1(bufB, vn, nvec, mu4, sg4, wt4);
            phase1(bufA, lik);
            load_g2(bufB, vn, nvec, pp4, mu4, sg4, wt4);
            phase2(bufA, lik, a);
        }
    }
    if (n > 0) {
        if (i & 1) { phase0(bufB, lik); phase1(bufB, lik); phase2(bufB, lik, a); }
        else       { phase0(bufA, lik); phase1(bufA, lik); phase2(bufA, lik, a); }
    }

    // Scalar tail (B not divisible by 4) — robustness; no-op for B = 4M.
    int tail = B & 3;
    if (tail) {
        int base = nvec << 2;
        if (idx < tail) {
            int j = base + idx;
            process_scalar(pp[j], tv[j],
                           mu[0 * B + j], sg[0 * B + j], wt[0 * B + j],
                           mu[1 * B + j], sg[1 * B + j], wt[1 * B + j],
                           mu[2 * B + j], sg[2 * B + j], wt[2 * B + j], a);
        }
    }

    // ---- Block reduction (all float, shuffle + tiny smem) ----
    #pragma unroll
    for (int o = 16; o > 0; o >>= 1) {
        a.p  += __shfl_down_sync(0xffffffffu, a.p,  o);
        a.ll += __shfl_down_sync(0xffffffffu, a.ll, o);
        a.np += __shfl_down_sync(0xffffffffu, a.np, o);
    }

    __shared__ float shp[NWARP], shl[NWARP], shn[NWARP];
    __shared__ bool s_last;
    int wid  = threadIdx.x >> 5;
    int lane = threadIdx.x & 31;
    if (lane == 0) { shp[wid] = a.p; shl[wid] = a.ll; shn[wid] = a.np; }
    __syncthreads();

    if (threadIdx.x == 0) {
        float vp = 0.f, vl = 0.f, vn = 0.f;
        #pragma unroll
        for (int k = 0; k < NWARP; k++) { vp += shp[k]; vl += shl[k]; vn += shn[k]; }
        g_part_p[blockIdx.x]  = vp;
        g_part_ll[blockIdx.x] = vl;
        g_part_np[blockIdx.x] = vn;
        __threadfence();
        unsigned t = atomicAdd(&g_ticket, 1u);
        s_last = (t == (unsigned)(NBLK - 1));
        if (s_last) g_ticket = 0u;   // self-reset: deterministic across replays
    }
    __syncthreads();

    // ---- Last block finalizes (float, 296 partials) ----
    if (s_last) {
        float sp = 0.f, sl = 0.f, sn = 0.f;
        for (int k = threadIdx.x; k < NBLK; k += NTHR) {
            sp += g_part_p[k];
            sl += g_part_ll[k];
            sn += g_part_np[k];
        }
        #pragma unroll
        for (int o = 16; o > 0; o >>= 1) {
            sp += __shfl_down_sync(0xffffffffu, sp, o);
            sl += __shfl_down_sync(0xffffffffu, sl, o);
            sn += __shfl_down_sync(0xffffffffu, sn, o);
        }
        if (lane == 0) { shp[wid] = sp; shl[wid] = sl; shn[wid] = sn; }
        __syncthreads();
        if (threadIdx.x == 0) {
            float vp = 0.f, vl = 0.f, vn = 0.f;
            #pragma unroll
            for (int k = 0; k < NWARP; k++) { vp += shp[k]; vl += shl[k]; vn += shn[k]; }
            float purchase = vp / (float)B;
            float ltv = (vn > 0.f) ? -(vl / fmaxf(vn, 1.f)) : 0.f;
            out[0] = purchase + ltv;
        }
    }
}

extern "C" void kernel_launch(void* const* d_in, const int* in_sizes, int n_in,
                              void* d_out, int out_size)
{
    const float* pp = (const float*)d_in[0];  // predicted_purchase_prob (B,)
    const float* mu = (const float*)d_in[1];  // mu     (K,B)
    const float* sg = (const float*)d_in[2];  // sigma  (K,B)
    const float* wt = (const float*)d_in[3];  // weight (K,B)
    const float* tv = (const float*)d_in[4];  // true_values (B,)
    int B = in_sizes[0];

    zimol_fused<<<NBLK, NTHR>>>(pp, mu, sg, wt, tv, (float*)d_out, B);
}